// round 15
// baseline (speedup 1.0000x reference)
#include <cuda_runtime.h>
#include <cuda_fp16.h>
#include <cstdint>

#define NFR 8
#define NO 197
#define NB 8
#define NTOK 1576          // 8*197
#define CDIM 768
#define NH 12
#define HD 64
#define MG 204             // gathered tokens
#define ROWS_X 12608       // 64*197
#define ROWS_KV 1632       // 8*204

// ---------------- scratch (no allocs allowed -> device globals) -------------
__device__ int    g_idx[MG];
__device__ __half g_Xh[ROWS_X * CDIM];
__device__ __half g_Wh[3 * CDIM * CDIM];
__device__ __half g_Ph[CDIM * CDIM];
__device__ __half g_Q16[ROWS_X * CDIM];        // Q projection (x0.125), fp16
__device__ __half g_KV16[ROWS_KV * 2 * CDIM];  // [K(768) | V(768)] fp16
__device__ __half g_AOh[ROWS_X * CDIM];

// ---------------------------------------------------------------------------
// One launch: build gather indices + convert x, qkv_w, proj_w to fp16.
// ---------------------------------------------------------------------------
#define N4X (ROWS_X * CDIM / 4)
#define N4W (3 * CDIM * CDIM / 4)
#define N4P (CDIM * CDIM / 4)
#define N4ALL (N4X + N4W + N4P)

__global__ void prep_kernel(const float* __restrict__ x,
                            const float* __restrict__ qkv_w,
                            const float* __restrict__ proj_w) {
    int i = blockIdx.x * blockDim.x + threadIdx.x;
    if (i < MG) {
        int m = i;
        if (m < NFR) g_idx[m] = m * NO;
        else {
            int mm = m - NFR;
            int f, j;
            if (mm < 100) { f = mm / 25; j = mm - f * 25; }
            else          { f = 4 + (mm - 100) / 24; j = (mm - 100) - (f - 4) * 24; }
            g_idx[m] = f * NO + 1 + f + 8 * j;
        }
    }
    if (i >= N4ALL) return;
    const float* src; __half* dst; int k;
    if (i < N4X)            { src = x;      dst = g_Xh; k = i; }
    else if (i < N4X + N4W) { src = qkv_w;  dst = g_Wh; k = i - N4X; }
    else                    { src = proj_w; dst = g_Ph; k = i - N4X - N4W; }
    float4 v = ((const float4*)src)[k];
    __half2 h0, h1;
    h0.x = __float2half(v.x); h0.y = __float2half(v.y);
    h1.x = __float2half(v.z); h1.y = __float2half(v.w);
    ((__half2*)dst)[2 * k]     = h0;
    ((__half2*)dst)[2 * k + 1] = h1;
}

// ---------------------------------------------------------------------------
// warp-mma helpers (base sm_103 PTX -- tcgen05 is a-gated, unavailable here)
// ---------------------------------------------------------------------------
__device__ __forceinline__ uint32_t smem_u32(const void* p) {
    uint32_t a;
    asm("{ .reg .u64 t; cvta.to.shared.u64 t, %1; cvt.u32.u64 %0, t; }"
        : "=r"(a) : "l"(p));
    return a;
}
#define LDSM_X4(r0, r1, r2, r3, addr)                                        \
    asm volatile("ldmatrix.sync.aligned.m8n8.x4.shared.b16 {%0,%1,%2,%3}, [%4];" \
                 : "=r"(r0), "=r"(r1), "=r"(r2), "=r"(r3) : "r"(addr))
#define LDSM_X4_T(r0, r1, r2, r3, addr)                                      \
    asm volatile("ldmatrix.sync.aligned.m8n8.x4.trans.shared.b16 {%0,%1,%2,%3}, [%4];" \
                 : "=r"(r0), "=r"(r1), "=r"(r2), "=r"(r3) : "r"(addr))
#define MMA16816(d, a, b0, b1)                                               \
    asm volatile("mma.sync.aligned.m16n8k16.row.col.f32.f16.f16.f32 "        \
                 "{%0,%1,%2,%3}, {%4,%5,%6,%7}, {%8,%9}, {%0,%1,%2,%3};"     \
                 : "+f"((d)[0]), "+f"((d)[1]), "+f"((d)[2]), "+f"((d)[3])    \
                 : "r"((a)[0]), "r"((a)[1]), "r"((a)[2]), "r"((a)[3]),       \
                   "r"(b0), "r"(b1))
#define CP_ASYNC16(dst, src)                                                 \
    asm volatile("cp.async.cg.shared.global [%0], [%1], 16;"                 \
                 :: "r"(dst), "l"(src))
#define CP_COMMIT()  asm volatile("cp.async.commit_group;" ::: "memory")
#define CP_WAIT0()   asm volatile("cp.async.wait_group 0;" ::: "memory")
#define CP_WAIT1()   asm volatile("cp.async.wait_group 1;" ::: "memory")

// ---------------------------------------------------------------------------
// GEMM body: C[128x256 tile @ (bm,bn)] = alpha * A @ B^T (+bias).
// Single-product fp16, BK=64, 8 warps with 64x64 warp tiles (2x4 grid),
// 2-stage cp.async double buffer, one barrier per chunk. 1 CTA/SM.
// Arithmetic intensity: 8 LDSM / 32 MMA per warp-ks (vs 6/16 before) ->
// smem crossbar demand drops below tensor demand.
// ---------------------------------------------------------------------------
#define LDS_PAD 72
#define ARR_A (128 * LDS_PAD)
#define ARR_B (256 * LDS_PAD)
#define BUF_ELEMS (ARR_A + ARR_B)
#define GEMM_SMEM (2 * BUF_ELEMS * 2)      // bytes (110592)

__device__ __forceinline__
void gemm_body(const __half* __restrict__ Ah, const __half* __restrict__ Bh,
               void* __restrict__ Cout, int M, int N,
               const float* __restrict__ bias, float alpha, int gather,
               int out_half, int bm, int bn, __half* smem)
{
    const int tid = threadIdx.x;
    const int wid = tid >> 5, lane = tid & 31;
    const int warp_m = wid & 1, warp_n = wid >> 1;   // 2 x 4 warps, 64x64 tiles
    const uint32_t sbase = smem_u32(smem);

    float acc[4][8][4];
#pragma unroll
    for (int mt = 0; mt < 4; mt++)
#pragma unroll
        for (int nt = 0; nt < 8; nt++)
#pragma unroll
            for (int e = 0; e < 4; e++) acc[mt][nt][e] = 0.f;

    const int a_row  = lane & 15;
    const int a_koff = (lane >> 4) << 3;
    const int b_row  = ((lane >> 4) << 3) + (lane & 7);
    const int b_koff = ((lane >> 3) & 1) << 3;

    auto stage = [&](int c, int buf) {
        const int k0 = c * 64;
        // A: 128 rows x 8 slots = 1024 ops; B: 256 rows x 8 slots = 2048 ops
#pragma unroll
        for (int t = 0; t < 12; t++) {
            int i = tid + 256 * t;       // [0,3072)
            const __half* src;
            int r, row, slot;
            uint32_t sm_off;
            if (i < 1024) {
                row = i >> 3; slot = i & 7;
                r = bm + row; if (r >= M) r = 0;
                if (gather) { int bb = r / MG; int mm = r - bb * MG; r = bb * NTOK + g_idx[mm]; }
                src = Ah;
                sm_off = (uint32_t)(buf * BUF_ELEMS + row * LDS_PAD + slot * 8);
            } else {
                int j = i - 1024;
                row = j >> 3; slot = j & 7;
                r = bn + row;
                src = Bh;
                sm_off = (uint32_t)(buf * BUF_ELEMS + ARR_A + row * LDS_PAD + slot * 8);
            }
            CP_ASYNC16(sbase + sm_off * 2, src + (size_t)r * CDIM + k0 + slot * 8);
        }
        CP_COMMIT();
    };

    stage(0, 0);

    for (int c = 0; c < 12; c++) {
        const int buf = c & 1;
        CP_WAIT0();
        __syncthreads();
        if (c + 1 < 12) stage(c + 1, buf ^ 1);

        const uint32_t sA = sbase + (uint32_t)(buf * BUF_ELEMS) * 2;
        const uint32_t sB = sA + ARR_A * 2;

#pragma unroll
        for (int ks = 0; ks < 4; ks++) {
            const int kb = ks * 16;
            uint32_t bh[4][4], af[4][4];
#pragma unroll
            for (int g = 0; g < 4; g++) {
                uint32_t off = (uint32_t)((warp_n * 64 + g * 16 + b_row) * LDS_PAD + kb + b_koff) * 2;
                LDSM_X4(bh[g][0], bh[g][1], bh[g][2], bh[g][3], sB + off);
            }
#pragma unroll
            for (int mt = 0; mt < 4; mt++) {
                uint32_t off = (uint32_t)((warp_m * 64 + mt * 16 + a_row) * LDS_PAD + kb + a_koff) * 2;
                LDSM_X4(af[mt][0], af[mt][1], af[mt][2], af[mt][3], sA + off);
            }
#pragma unroll
            for (int mt = 0; mt < 4; mt++)
#pragma unroll
                for (int g = 0; g < 4; g++) {
                    MMA16816(acc[mt][2 * g],     af[mt], bh[g][0], bh[g][1]);
                    MMA16816(acc[mt][2 * g + 1], af[mt], bh[g][2], bh[g][3]);
                }
        }
        // no bottom barrier: buf only overwritten after the NEXT top barrier
    }

    const int qrow = lane >> 2, qcol = (lane & 3) * 2;
#pragma unroll
    for (int mt = 0; mt < 4; mt++) {
#pragma unroll
        for (int half = 0; half < 2; half++) {
            int r = bm + warp_m * 64 + mt * 16 + qrow + half * 8;
            if (r >= M) continue;
#pragma unroll
            for (int nt = 0; nt < 8; nt++) {
                int cc = bn + warp_n * 64 + nt * 8 + qcol;
                float ox = acc[mt][nt][2 * half]     * alpha;
                float oy = acc[mt][nt][2 * half + 1] * alpha;
                if (out_half) {
                    __half2 hv;
                    hv.x = __float2half(ox); hv.y = __float2half(oy);
                    *(__half2*)((__half*)Cout + (size_t)r * N + cc) = hv;
                } else {
                    float2 o;
                    o.x = ox + (bias ? bias[cc]     : 0.f);
                    o.y = oy + (bias ? bias[cc + 1] : 0.f);
                    *(float2*)((float*)Cout + (size_t)r * N + cc) = o;
                }
            }
        }
    }
}

// ---- merged Q + KV projection ----
#define QTILES_M 99            // ceil(12608/128)
#define QN_TILES 3             // 768/256
#define QBLOCKS (QTILES_M * QN_TILES)   // 297
#define KVTILES_M 13           // ceil(1632/128)
#define KVN_TILES 6            // 1536/256
#define KVBLOCKS (KVTILES_M * KVN_TILES)

__global__ __launch_bounds__(256)
void gemm_qkv_kernel() {
    extern __shared__ __half smem[];
    int bid = blockIdx.x;
    if (bid < QBLOCKS) {
        int bm = (bid / QN_TILES) * 128, bn = (bid % QN_TILES) * 256;
        gemm_body(g_Xh, g_Wh, g_Q16, ROWS_X, CDIM,
                  nullptr, 0.125f, 0, 1, bm, bn, smem);
    } else {
        bid -= QBLOCKS;
        int bm = (bid % KVTILES_M) * 128, bn = (bid / KVTILES_M) * 256;
        gemm_body(g_Xh, g_Wh + CDIM * CDIM, g_KV16, ROWS_KV, 2 * CDIM,
                  nullptr, 1.f, 1, 1, bm, bn, smem);
    }
}

// ---- output projection ----
__global__ __launch_bounds__(256)
void gemm_proj_kernel(float* __restrict__ out, const float* __restrict__ bias) {
    extern __shared__ __half smem[];
    int bid = blockIdx.x;
    int bm = (bid / QN_TILES) * 128, bn = (bid % QN_TILES) * 256;
    gemm_body(g_AOh, g_Ph, out, ROWS_X, CDIM, bias, 1.f, 0, 0, bm, bn, smem);
}

// ---------------------------------------------------------------------------
// Tensor-core fused attention. Block = 256 threads (8 warps), one (b, h,
// 128-row q-tile). Warp w owns rows 16w..16w+15 over 208 key columns
// (204 real + 4 masked pad). Two cp.async groups: (Q,K) then (V).
// ---------------------------------------------------------------------------
#define ALD 72
#define QROWS 128
#define ATTN_SMEM ((QROWS + 208 + 208) * ALD * 2)   // bytes

__global__ __launch_bounds__(256) void attn_mma_kernel() {
    extern __shared__ __half sm16[];
    const int b = blockIdx.z, h = blockIdx.y;
    const int n0 = blockIdx.x * QROWS;
    const int tid = threadIdx.x, w = tid >> 5, lane = tid & 31;
    const uint32_t sb = smem_u32(sm16);

    // ---- group 1: Q (128x64) + K (208x64) ----
#pragma unroll
    for (int t = 0; t < 4; t++) {
        int i = tid + 256 * t;
        int r = i >> 3, q = i & 7;
        int n = n0 + r; if (n >= NTOK) n = NTOK - 1;
        const __half* src = g_Q16 + (size_t)(b * NTOK + n) * CDIM + h * HD + q * 8;
        CP_ASYNC16(sb + (uint32_t)(r * ALD + q * 8) * 2, src);
    }
#pragma unroll
    for (int t = 0; t < 7; t++) {
        int i = tid + 256 * t;
        if (i < 1664) {
            int m = i >> 3, q = i & 7;
            int mc = m < MG ? m : MG - 1;
            const __half* base = g_KV16 + (size_t)(b * MG + mc) * (2 * CDIM) + h * HD + q * 8;
            CP_ASYNC16(sb + (uint32_t)((QROWS + m) * ALD + q * 8) * 2, base);
        }
    }
    CP_COMMIT();
    // ---- group 2: V (208x64) ----
#pragma unroll
    for (int t = 0; t < 7; t++) {
        int i = tid + 256 * t;
        if (i < 1664) {
            int m = i >> 3, q = i & 7;
            int mc = m < MG ? m : MG - 1;
            const __half* base = g_KV16 + (size_t)(b * MG + mc) * (2 * CDIM) + h * HD + CDIM + q * 8;
            CP_ASYNC16(sb + (uint32_t)((QROWS + 208 + m) * ALD + q * 8) * 2, base);
        }
    }
    CP_COMMIT();

    CP_WAIT1();                 // Q + K ready
    __syncthreads();

    const int a_row  = lane & 15;
    const int a_koff = (lane >> 4) << 3;
    const int b_row  = ((lane >> 4) << 3) + (lane & 7);
    const int b_koff = ((lane >> 3) & 1) << 3;

    float s[26][4];
#pragma unroll
    for (int nt = 0; nt < 26; nt++)
#pragma unroll
        for (int e = 0; e < 4; e++) s[nt][e] = 0.f;

#pragma unroll
    for (int ks = 0; ks < 4; ks++) {
        const int kb = ks * 16;
        uint32_t af[4];
        LDSM_X4(af[0], af[1], af[2], af[3],
                sb + (uint32_t)((w * 16 + a_row) * ALD + kb + a_koff) * 2);
#pragma unroll
        for (int g = 0; g < 13; g++) {
            uint32_t b0, b1, b2, b3;
            LDSM_X4(b0, b1, b2, b3,
                    sb + (uint32_t)((QROWS + g * 16 + b_row) * ALD + kb + b_koff) * 2);
            MMA16816(s[2 * g],     af, b0, b1);
            MMA16816(s[2 * g + 1], af, b2, b3);
        }
    }

    const int qrow = lane >> 2;
    const int nrow0 = n0 + w * 16 + qrow;
    const int nrow1 = nrow0 + 8;
    const int nf0 = (nrow0 < NTOK) ? nrow0 / NO : 0;
    const int nf1 = (nrow1 < NTOK) ? nrow1 / NO : 0;

    float mx0 = -1e30f, mx1 = -1e30f;
#pragma unroll
    for (int nt = 0; nt < 26; nt++) {
#pragma unroll
        for (int e = 0; e < 2; e++) {
            int c = nt * 8 + (lane & 3) * 2 + e;
            if (c >= MG) { s[nt][e] = -1e30f; s[nt][2 + e] = -1e30f; continue; }
            if (c >= NFR) {
                int mm = c - NFR;
                int f = (mm < 100) ? mm / 25 : 4 + (mm - 100) / 24;
                if (f != nf0) s[nt][e]     *= 0.8f;
                if (f != nf1) s[nt][2 + e] *= 0.8f;
            }
            mx0 = fmaxf(mx0, s[nt][e]);
            mx1 = fmaxf(mx1, s[nt][2 + e]);
        }
    }
    mx0 = fmaxf(mx0, __shfl_xor_sync(0xffffffffu, mx0, 1));
    mx0 = fmaxf(mx0, __shfl_xor_sync(0xffffffffu, mx0, 2));
    mx1 = fmaxf(mx1, __shfl_xor_sync(0xffffffffu, mx1, 1));
    mx1 = fmaxf(mx1, __shfl_xor_sync(0xffffffffu, mx1, 2));

    float sum0 = 0.f, sum1 = 0.f;
    uint32_t p2[26][2];
#pragma unroll
    for (int nt = 0; nt < 26; nt++) {
        float e0 = __expf(s[nt][0] - mx0);
        float e1 = __expf(s[nt][1] - mx0);
        float e2 = __expf(s[nt][2] - mx1);
        float e3 = __expf(s[nt][3] - mx1);
        sum0 += e0 + e1; sum1 += e2 + e3;
        __half2 lo, hi;
        lo.x = __float2half(e0); lo.y = __float2half(e1);
        hi.x = __float2half(e2); hi.y = __float2half(e3);
        p2[nt][0] = *(uint32_t*)&lo;
        p2[nt][1] = *(uint32_t*)&hi;
    }
    sum0 += __shfl_xor_sync(0xffffffffu, sum0, 1);
    sum0 += __shfl_xor_sync(0xffffffffu, sum0, 2);
    sum1 += __shfl_xor_sync(0xffffffffu, sum1, 1);
    sum1 += __shfl_xor_sync(0xffffffffu, sum1, 2);
    const float inv0 = 1.f / sum0, inv1 = 1.f / sum1;

    CP_WAIT0();                 // V ready
    __syncthreads();

    float o[8][4];
#pragma unroll
    for (int nt = 0; nt < 8; nt++)
#pragma unroll
        for (int e = 0; e < 4; e++) o[nt][e] = 0.f;

#pragma unroll
    for (int ng = 0; ng < 4; ng++) {
#pragma unroll
        for (int kk = 0; kk < 13; kk++) {
            uint32_t v0, v1, v2, v3;
            LDSM_X4_T(v0, v1, v2, v3,
                      sb + (uint32_t)((QROWS + 208 + kk * 16 + (lane & 15)) * ALD
                                      + ng * 16 + ((lane >> 4) << 3)) * 2);
            uint32_t af[4] = { p2[2 * kk][0], p2[2 * kk][1],
                               p2[2 * kk + 1][0], p2[2 * kk + 1][1] };
            MMA16816(o[2 * ng],     af, v0, v1);
            MMA16816(o[2 * ng + 1], af, v2, v3);
        }
    }

    if (nrow0 < NTOK) {
        __half* dst = g_AOh + (size_t)(b * NTOK + nrow0) * CDIM + h * HD;
#pragma unroll
        for (int nt = 0; nt < 8; nt++) {
            int d = nt * 8 + (lane & 3) * 2;
            __half2 hv;
            hv.x = __float2half(o[nt][0] * inv0);
            hv.y = __float2half(o[nt][1] * inv0);
            *(__half2*)(dst + d) = hv;
        }
    }
    if (nrow1 < NTOK) {
        __half* dst = g_AOh + (size_t)(b * NTOK + nrow1) * CDIM + h * HD;
#pragma unroll
        for (int nt = 0; nt < 8; nt++) {
            int d = nt * 8 + (lane & 3) * 2;
            __half2 hv;
            hv.x = __float2half(o[nt][2] * inv1);
            hv.y = __float2half(o[nt][3] * inv1);
            *(__half2*)(dst + d) = hv;
        }
    }
}

// ---------------------------------------------------------------------------
extern "C" void kernel_launch(void* const* d_in, const int* in_sizes, int n_in,
                              void* d_out, int out_size) {
    const float* x      = (const float*)d_in[0];
    const float* qkv_w  = (const float*)d_in[1];
    const float* proj_w = (const float*)d_in[2];
    const float* proj_b = (const float*)d_in[3];
    float* out = (float*)d_out;

    cudaFuncSetAttribute(gemm_qkv_kernel, cudaFuncAttributeMaxDynamicSharedMemorySize, GEMM_SMEM);
    cudaFuncSetAttribute(gemm_proj_kernel, cudaFuncAttributeMaxDynamicSharedMemorySize, GEMM_SMEM);
    cudaFuncSetAttribute(attn_mma_kernel, cudaFuncAttributeMaxDynamicSharedMemorySize, ATTN_SMEM);

    // prep: gather indices + all fp16 conversions
    prep_kernel<<<(N4ALL + 255) / 256, 256>>>(x, qkv_w, proj_w);

    // merged Q + KV projections
    gemm_qkv_kernel<<<QBLOCKS + KVBLOCKS, 256, GEMM_SMEM>>>();

    // fused tensor-core attention -> fp16 AO
    dim3 ga((NTOK + QROWS - 1) / QROWS, NH, NB);
    attn_mma_kernel<<<ga, 256, ATTN_SMEM>>>();

    // out = AO @ proj_w^T + proj_b  (fp32)
    gemm_proj_kernel<<<QBLOCKS, 256, GEMM_SMEM>>>(out, proj_b);
}

// round 16
// speedup vs baseline: 1.1344x; 1.1344x over previous
#include <cuda_runtime.h>
#include <cuda_fp16.h>
#include <cstdint>

#define NFR 8
#define NO 197
#define NB 8
#define NTOK 1576          // 8*197
#define CDIM 768
#define NH 12
#define HD 64
#define MG 204             // gathered tokens
#define ROWS_X 12608       // 64*197
#define ROWS_KV 1632       // 8*204

// ---------------- scratch (no allocs allowed -> device globals) -------------
__device__ int    g_idx[MG];
__device__ __half g_Xh[ROWS_X * CDIM];
__device__ __half g_Wh[3 * CDIM * CDIM];
__device__ __half g_Ph[CDIM * CDIM];
__device__ __half g_Q16[ROWS_X * CDIM];        // Q projection (x0.125), fp16
__device__ __half g_KV16[ROWS_KV * 2 * CDIM];  // [K(768) | V(768)] fp16
__device__ __half g_AOh[ROWS_X * CDIM];

// ---------------------------------------------------------------------------
// One launch: build gather indices + convert x, qkv_w, proj_w to fp16.
// ---------------------------------------------------------------------------
#define N4X (ROWS_X * CDIM / 4)
#define N4W (3 * CDIM * CDIM / 4)
#define N4P (CDIM * CDIM / 4)
#define N4ALL (N4X + N4W + N4P)

__global__ void prep_kernel(const float* __restrict__ x,
                            const float* __restrict__ qkv_w,
                            const float* __restrict__ proj_w) {
    int i = blockIdx.x * blockDim.x + threadIdx.x;
    if (i < MG) {
        int m = i;
        if (m < NFR) g_idx[m] = m * NO;
        else {
            int mm = m - NFR;
            int f, j;
            if (mm < 100) { f = mm / 25; j = mm - f * 25; }
            else          { f = 4 + (mm - 100) / 24; j = (mm - 100) - (f - 4) * 24; }
            g_idx[m] = f * NO + 1 + f + 8 * j;
        }
    }
    if (i >= N4ALL) return;
    const float* src; __half* dst; int k;
    if (i < N4X)            { src = x;      dst = g_Xh; k = i; }
    else if (i < N4X + N4W) { src = qkv_w;  dst = g_Wh; k = i - N4X; }
    else                    { src = proj_w; dst = g_Ph; k = i - N4X - N4W; }
    float4 v = ((const float4*)src)[k];
    __half2 h0, h1;
    h0.x = __float2half(v.x); h0.y = __float2half(v.y);
    h1.x = __float2half(v.z); h1.y = __float2half(v.w);
    ((__half2*)dst)[2 * k]     = h0;
    ((__half2*)dst)[2 * k + 1] = h1;
}

// ---------------------------------------------------------------------------
// warp-mma helpers (base sm_103 PTX -- tcgen05 is a-gated, unavailable here)
// ---------------------------------------------------------------------------
__device__ __forceinline__ uint32_t smem_u32(const void* p) {
    uint32_t a;
    asm("{ .reg .u64 t; cvta.to.shared.u64 t, %1; cvt.u32.u64 %0, t; }"
        : "=r"(a) : "l"(p));
    return a;
}
#define LDSM_X4(r0, r1, r2, r3, addr)                                        \
    asm volatile("ldmatrix.sync.aligned.m8n8.x4.shared.b16 {%0,%1,%2,%3}, [%4];" \
                 : "=r"(r0), "=r"(r1), "=r"(r2), "=r"(r3) : "r"(addr))
#define LDSM_X4_T(r0, r1, r2, r3, addr)                                      \
    asm volatile("ldmatrix.sync.aligned.m8n8.x4.trans.shared.b16 {%0,%1,%2,%3}, [%4];" \
                 : "=r"(r0), "=r"(r1), "=r"(r2), "=r"(r3) : "r"(addr))
#define MMA16816(d, a, b0, b1)                                               \
    asm volatile("mma.sync.aligned.m16n8k16.row.col.f32.f16.f16.f32 "        \
                 "{%0,%1,%2,%3}, {%4,%5,%6,%7}, {%8,%9}, {%0,%1,%2,%3};"     \
                 : "+f"((d)[0]), "+f"((d)[1]), "+f"((d)[2]), "+f"((d)[3])    \
                 : "r"((a)[0]), "r"((a)[1]), "r"((a)[2]), "r"((a)[3]),       \
                   "r"(b0), "r"(b1))
#define CP_ASYNC16(dst, src)                                                 \
    asm volatile("cp.async.cg.shared.global [%0], [%1], 16;"                 \
                 :: "r"(dst), "l"(src))
#define CP_COMMIT()  asm volatile("cp.async.commit_group;" ::: "memory")
#define CP_WAIT0()   asm volatile("cp.async.wait_group 0;" ::: "memory")
#define CP_WAIT1()   asm volatile("cp.async.wait_group 1;" ::: "memory")

// ---------------------------------------------------------------------------
// GEMM body: C[128x128 tile @ (bm,bn)] = alpha * A @ B^T (+bias).
// Single-product fp16, BK=64, 8 warps (32x64 warp tiles), 3-stage cp.async
// pipeline with wait_group 1 (one group always in flight), one barrier per
// chunk, fully-unrolled buffer indices. 2 CTAs/SM.
// ---------------------------------------------------------------------------
#define LDS_PAD 72
#define ARR_ELEMS (128 * LDS_PAD)
#define BUF_ELEMS (2 * ARR_ELEMS)          // Ah | Bh
#define NSTAGE 3
#define GEMM_SMEM (NSTAGE * BUF_ELEMS * 2) // bytes (110592)

__device__ __forceinline__
void gemm_body(const __half* __restrict__ Ah, const __half* __restrict__ Bh,
               void* __restrict__ Cout, int M, int N,
               const float* __restrict__ bias, float alpha, int gather,
               int out_half, int bm, int bn, __half* smem)
{
    const int tid = threadIdx.x;
    const int wid = tid >> 5, lane = tid & 31;
    const int warp_m = wid & 3, warp_n = wid >> 2;
    const uint32_t sbase = smem_u32(smem);

    float acc[2][8][4];
#pragma unroll
    for (int mt = 0; mt < 2; mt++)
#pragma unroll
        for (int nt = 0; nt < 8; nt++)
#pragma unroll
            for (int e = 0; e < 4; e++) acc[mt][nt][e] = 0.f;

    const int a_row  = lane & 15;
    const int a_koff = (lane >> 4) << 3;
    const int b_row  = ((lane >> 4) << 3) + (lane & 7);
    const int b_koff = ((lane >> 3) & 1) << 3;

    auto stage = [&](int c, int buf) {
        const int k0 = c * 64;
#pragma unroll
        for (int t = 0; t < 8; t++) {
            int i = tid + 256 * t;       // [0,2048)
            int a = i >> 10, row = (i >> 3) & 127, slot = i & 7;
            const __half* src;
            int r;
            if (a == 0) {
                r = bm + row; if (r >= M) r = 0;
                if (gather) { int bb = r / MG; int mm = r - bb * MG; r = bb * NTOK + g_idx[mm]; }
                src = Ah;
            } else {
                r = bn + row;
                src = Bh;
            }
            uint32_t dst = sbase +
                (uint32_t)(buf * BUF_ELEMS + a * ARR_ELEMS + row * LDS_PAD + slot * 8) * 2;
            CP_ASYNC16(dst, src + (size_t)r * CDIM + k0 + slot * 8);
        }
        CP_COMMIT();
    };

    auto compute = [&](int buf) {
        const uint32_t sA = sbase + (uint32_t)(buf * BUF_ELEMS) * 2;
        const uint32_t sB = sA + ARR_ELEMS * 2;
#pragma unroll
        for (int ks = 0; ks < 4; ks++) {
            const int kb = ks * 16;
            uint32_t bh[4][4], af[2][4];
#pragma unroll
            for (int g = 0; g < 4; g++) {
                uint32_t off = (uint32_t)((warp_n * 64 + g * 16 + b_row) * LDS_PAD + kb + b_koff) * 2;
                LDSM_X4(bh[g][0], bh[g][1], bh[g][2], bh[g][3], sB + off);
            }
#pragma unroll
            for (int mt = 0; mt < 2; mt++) {
                uint32_t off = (uint32_t)((warp_m * 32 + mt * 16 + a_row) * LDS_PAD + kb + a_koff) * 2;
                LDSM_X4(af[mt][0], af[mt][1], af[mt][2], af[mt][3], sA + off);
            }
#pragma unroll
            for (int mt = 0; mt < 2; mt++)
#pragma unroll
                for (int g = 0; g < 4; g++) {
                    MMA16816(acc[mt][2 * g],     af[mt], bh[g][0], bh[g][1]);
                    MMA16816(acc[mt][2 * g + 1], af[mt], bh[g][2], bh[g][3]);
                }
        }
    };

    stage(0, 0);
    stage(1, 1);

    // 12 chunks, unrolled x3 so buffer indices are compile-time constants.
#pragma unroll
    for (int cc = 0; cc < 4; cc++) {
#pragma unroll
        for (int sub = 0; sub < 3; sub++) {
            const int c = cc * 3 + sub;
            if (c == 11) { CP_WAIT0(); } else { CP_WAIT1(); }
            __syncthreads();
            if (c + 2 < 12) stage(c + 2, (sub + 2) % 3);
            compute(sub);
            // no bottom barrier: buf(sub) only overwritten by stage(c+3)
            // after the NEXT iteration's top barrier.
        }
    }

    const int qrow = lane >> 2, qcol = (lane & 3) * 2;
#pragma unroll
    for (int mt = 0; mt < 2; mt++) {
#pragma unroll
        for (int half = 0; half < 2; half++) {
            int r = bm + warp_m * 32 + mt * 16 + qrow + half * 8;
            if (r >= M) continue;
#pragma unroll
            for (int nt = 0; nt < 8; nt++) {
                int cc = bn + warp_n * 64 + nt * 8 + qcol;
                float ox = acc[mt][nt][2 * half]     * alpha;
                float oy = acc[mt][nt][2 * half + 1] * alpha;
                if (out_half) {
                    __half2 hv;
                    hv.x = __float2half(ox); hv.y = __float2half(oy);
                    *(__half2*)((__half*)Cout + (size_t)r * N + cc) = hv;
                } else {
                    float2 o;
                    o.x = ox + (bias ? bias[cc]     : 0.f);
                    o.y = oy + (bias ? bias[cc + 1] : 0.f);
                    *(float2*)((float*)Cout + (size_t)r * N + cc) = o;
                }
            }
        }
    }
}

// ---- merged Q + KV projection (750 linearized CTAs) ----
#define QTILES_M 99            // ceil(12608/128)
#define QBLOCKS (QTILES_M * 6) // 594
#define KVTILES_M 13           // ceil(1632/128)
#define KVBLOCKS (KVTILES_M * 12)

__global__ __launch_bounds__(256, 2)
void gemm_qkv_kernel() {
    extern __shared__ __half smem[];
    int bid = blockIdx.x;
    if (bid < QBLOCKS) {
        int bm = (bid / 6) * 128, bn = (bid % 6) * 128;
        gemm_body(g_Xh, g_Wh, g_Q16, ROWS_X, CDIM,
                  nullptr, 0.125f, 0, 1, bm, bn, smem);
    } else {
        bid -= QBLOCKS;
        int bm = (bid % KVTILES_M) * 128, bn = (bid / KVTILES_M) * 128;
        gemm_body(g_Xh, g_Wh + CDIM * CDIM, g_KV16, ROWS_KV, 2 * CDIM,
                  nullptr, 1.f, 1, 1, bm, bn, smem);
    }
}

// ---- output projection ----
__global__ __launch_bounds__(256, 2)
void gemm_proj_kernel(float* __restrict__ out, const float* __restrict__ bias) {
    extern __shared__ __half smem[];
    int bid = blockIdx.x;
    int bm = (bid / 6) * 128, bn = (bid % 6) * 128;
    gemm_body(g_AOh, g_Ph, out, ROWS_X, CDIM, bias, 1.f, 0, 0, bm, bn, smem);
}

// ---------------------------------------------------------------------------
// Tensor-core fused attention. Block = 256 threads (8 warps), one (b, h,
// 128-row q-tile). Warp w owns rows 16w..16w+15 over 208 key columns
// (204 real + 4 masked pad). Two cp.async groups: (Q,K) then (V).
// ---------------------------------------------------------------------------
#define ALD 72
#define QROWS 128
#define ATTN_SMEM ((QROWS + 208 + 208) * ALD * 2)   // bytes

__global__ __launch_bounds__(256) void attn_mma_kernel() {
    extern __shared__ __half sm16[];
    const int b = blockIdx.z, h = blockIdx.y;
    const int n0 = blockIdx.x * QROWS;
    const int tid = threadIdx.x, w = tid >> 5, lane = tid & 31;
    const uint32_t sb = smem_u32(sm16);

    // ---- group 1: Q (128x64) + K (208x64) ----
#pragma unroll
    for (int t = 0; t < 4; t++) {
        int i = tid + 256 * t;
        int r = i >> 3, q = i & 7;
        int n = n0 + r; if (n >= NTOK) n = NTOK - 1;
        const __half* src = g_Q16 + (size_t)(b * NTOK + n) * CDIM + h * HD + q * 8;
        CP_ASYNC16(sb + (uint32_t)(r * ALD + q * 8) * 2, src);
    }
#pragma unroll
    for (int t = 0; t < 7; t++) {
        int i = tid + 256 * t;
        if (i < 1664) {
            int m = i >> 3, q = i & 7;
            int mc = m < MG ? m : MG - 1;
            const __half* base = g_KV16 + (size_t)(b * MG + mc) * (2 * CDIM) + h * HD + q * 8;
            CP_ASYNC16(sb + (uint32_t)((QROWS + m) * ALD + q * 8) * 2, base);
        }
    }
    CP_COMMIT();
    // ---- group 2: V (208x64) ----
#pragma unroll
    for (int t = 0; t < 7; t++) {
        int i = tid + 256 * t;
        if (i < 1664) {
            int m = i >> 3, q = i & 7;
            int mc = m < MG ? m : MG - 1;
            const __half* base = g_KV16 + (size_t)(b * MG + mc) * (2 * CDIM) + h * HD + CDIM + q * 8;
            CP_ASYNC16(sb + (uint32_t)((QROWS + 208 + m) * ALD + q * 8) * 2, base);
        }
    }
    CP_COMMIT();

    CP_WAIT1();                 // Q + K ready
    __syncthreads();

    const int a_row  = lane & 15;
    const int a_koff = (lane >> 4) << 3;
    const int b_row  = ((lane >> 4) << 3) + (lane & 7);
    const int b_koff = ((lane >> 3) & 1) << 3;

    float s[26][4];
#pragma unroll
    for (int nt = 0; nt < 26; nt++)
#pragma unroll
        for (int e = 0; e < 4; e++) s[nt][e] = 0.f;

#pragma unroll
    for (int ks = 0; ks < 4; ks++) {
        const int kb = ks * 16;
        uint32_t af[4];
        LDSM_X4(af[0], af[1], af[2], af[3],
                sb + (uint32_t)((w * 16 + a_row) * ALD + kb + a_koff) * 2);
#pragma unroll
        for (int g = 0; g < 13; g++) {
            uint32_t b0, b1, b2, b3;
            LDSM_X4(b0, b1, b2, b3,
                    sb + (uint32_t)((QROWS + g * 16 + b_row) * ALD + kb + b_koff) * 2);
            MMA16816(s[2 * g],     af, b0, b1);
            MMA16816(s[2 * g + 1], af, b2, b3);
        }
    }

    const int qrow = lane >> 2;
    const int nrow0 = n0 + w * 16 + qrow;
    const int nrow1 = nrow0 + 8;
    const int nf0 = (nrow0 < NTOK) ? nrow0 / NO : 0;
    const int nf1 = (nrow1 < NTOK) ? nrow1 / NO : 0;

    float mx0 = -1e30f, mx1 = -1e30f;
#pragma unroll
    for (int nt = 0; nt < 26; nt++) {
#pragma unroll
        for (int e = 0; e < 2; e++) {
            int c = nt * 8 + (lane & 3) * 2 + e;
            if (c >= MG) { s[nt][e] = -1e30f; s[nt][2 + e] = -1e30f; continue; }
            if (c >= NFR) {
                int mm = c - NFR;
                int f = (mm < 100) ? mm / 25 : 4 + (mm - 100) / 24;
                if (f != nf0) s[nt][e]     *= 0.8f;
                if (f != nf1) s[nt][2 + e] *= 0.8f;
            }
            mx0 = fmaxf(mx0, s[nt][e]);
            mx1 = fmaxf(mx1, s[nt][2 + e]);
        }
    }
    mx0 = fmaxf(mx0, __shfl_xor_sync(0xffffffffu, mx0, 1));
    mx0 = fmaxf(mx0, __shfl_xor_sync(0xffffffffu, mx0, 2));
    mx1 = fmaxf(mx1, __shfl_xor_sync(0xffffffffu, mx1, 1));
    mx1 = fmaxf(mx1, __shfl_xor_sync(0xffffffffu, mx1, 2));

    float sum0 = 0.f, sum1 = 0.f;
    uint32_t p2[26][2];
#pragma unroll
    for (int nt = 0; nt < 26; nt++) {
        float e0 = __expf(s[nt][0] - mx0);
        float e1 = __expf(s[nt][1] - mx0);
        float e2 = __expf(s[nt][2] - mx1);
        float e3 = __expf(s[nt][3] - mx1);
        sum0 += e0 + e1; sum1 += e2 + e3;
        __half2 lo, hi;
        lo.x = __float2half(e0); lo.y = __float2half(e1);
        hi.x = __float2half(e2); hi.y = __float2half(e3);
        p2[nt][0] = *(uint32_t*)&lo;
        p2[nt][1] = *(uint32_t*)&hi;
    }
    sum0 += __shfl_xor_sync(0xffffffffu, sum0, 1);
    sum0 += __shfl_xor_sync(0xffffffffu, sum0, 2);
    sum1 += __shfl_xor_sync(0xffffffffu, sum1, 1);
    sum1 += __shfl_xor_sync(0xffffffffu, sum1, 2);
    const float inv0 = 1.f / sum0, inv1 = 1.f / sum1;

    CP_WAIT0();                 // V ready
    __syncthreads();

    float o[8][4];
#pragma unroll
    for (int nt = 0; nt < 8; nt++)
#pragma unroll
        for (int e = 0; e < 4; e++) o[nt][e] = 0.f;

#pragma unroll
    for (int ng = 0; ng < 4; ng++) {
#pragma unroll
        for (int kk = 0; kk < 13; kk++) {
            uint32_t v0, v1, v2, v3;
            LDSM_X4_T(v0, v1, v2, v3,
                      sb + (uint32_t)((QROWS + 208 + kk * 16 + (lane & 15)) * ALD
                                      + ng * 16 + ((lane >> 4) << 3)) * 2);
            uint32_t af[4] = { p2[2 * kk][0], p2[2 * kk][1],
                               p2[2 * kk + 1][0], p2[2 * kk + 1][1] };
            MMA16816(o[2 * ng],     af, v0, v1);
            MMA16816(o[2 * ng + 1], af, v2, v3);
        }
    }

    if (nrow0 < NTOK) {
        __half* dst = g_AOh + (size_t)(b * NTOK + nrow0) * CDIM + h * HD;
#pragma unroll
        for (int nt = 0; nt < 8; nt++) {
            int d = nt * 8 + (lane & 3) * 2;
            __half2 hv;
            hv.x = __float2half(o[nt][0] * inv0);
            hv.y = __float2half(o[nt][1] * inv0);
            *(__half2*)(dst + d) = hv;
        }
    }
    if (nrow1 < NTOK) {
        __half* dst = g_AOh + (size_t)(b * NTOK + nrow1) * CDIM + h * HD;
#pragma unroll
        for (int nt = 0; nt < 8; nt++) {
            int d = nt * 8 + (lane & 3) * 2;
            __half2 hv;
            hv.x = __float2half(o[nt][2] * inv1);
            hv.y = __float2half(o[nt][3] * inv1);
            *(__half2*)(dst + d) = hv;
        }
    }
}

// ---------------------------------------------------------------------------
extern "C" void kernel_launch(void* const* d_in, const int* in_sizes, int n_in,
                              void* d_out, int out_size) {
    const float* x      = (const float*)d_in[0];
    const float* qkv_w  = (const float*)d_in[1];
    const float* proj_w = (const float*)d_in[2];
    const float* proj_b = (const float*)d_in[3];
    float* out = (float*)d_out;

    cudaFuncSetAttribute(gemm_qkv_kernel, cudaFuncAttributeMaxDynamicSharedMemorySize, GEMM_SMEM);
    cudaFuncSetAttribute(gemm_proj_kernel, cudaFuncAttributeMaxDynamicSharedMemorySize, GEMM_SMEM);
    cudaFuncSetAttribute(attn_mma_kernel, cudaFuncAttributeMaxDynamicSharedMemorySize, ATTN_SMEM);

    // prep: gather indices + all fp16 conversions
    prep_kernel<<<(N4ALL + 255) / 256, 256>>>(x, qkv_w, proj_w);

    // merged Q + KV projections
    gemm_qkv_kernel<<<QBLOCKS + KVBLOCKS, 256, GEMM_SMEM>>>();

    // fused tensor-core attention -> fp16 AO
    dim3 ga((NTOK + QROWS - 1) / QROWS, NH, NB);
    attn_mma_kernel<<<ga, 256, ATTN_SMEM>>>();

    // out = AO @ proj_w^T + proj_b  (fp32)
    gemm_proj_kernel<<<QBLOCKS, 256, GEMM_SMEM>>>(out, proj_b);
}